// round 5
// baseline (speedup 1.0000x reference)
#include <cuda_runtime.h>
#include <math.h>

#define B 8
#define N 1024
#define C 256
#define K 256
#define C2 512
#define SCALE 0.17677669529663687f   // (C/H)^-0.5 = 1/sqrt(32)

// Output layout: [new_X (8*256*256) | new_adj (8*256*256) | new_mask (8*256)]
#define OUT_ADJ_OFF  (B*K*C)
#define OUT_MASK_OFF (2*B*K*C)

#define NCHUNK 64      // partial-sum chunks per batch (16 rows each)

// ---- scratch ----
__device__ float d_part[B*NCHUNK*C];
__device__ float d_u[B*C];
__device__ float d_scores[B*N];
__device__ int   d_idxg[B*K];
__device__ float d_gate[B*K];
__device__ float d_nm[B*K];

// ---------------------------------------------------------------------------
// K1: partial column sums of X (verbatim R2 — proven rounding).
// ---------------------------------------------------------------------------
__global__ void k_partial(const float* __restrict__ X) {
    int b = blockIdx.y, ch = blockIdx.x, c = threadIdx.x;
    const float* xp = X + ((size_t)b * N + (size_t)ch * 16) * C + c;
    float s = 0.f;
    #pragma unroll
    for (int r = 0; r < 16; r++) s += xp[(size_t)r * C];
    d_part[(b * NCHUNK + ch) * C + c] = s;
}

// ---------------------------------------------------------------------------
// K2: Xsum finish + two matvecs (verbatim R2 — proven rounding).
// ---------------------------------------------------------------------------
__global__ void k_uvec(const float* __restrict__ Wqkv) {
    int b = blockIdx.x, t = threadIdx.x;
    __shared__ float xs[C];
    __shared__ float ks[C];
    float s = 0.f;
    #pragma unroll
    for (int ch = 0; ch < NCHUNK; ch++) s += d_part[(b * NCHUNK + ch) * C + t];
    xs[t] = s;
    __syncthreads();
    float ka = 0.f;
    for (int c = 0; c < C; c++) ka += xs[c] * Wqkv[(size_t)c * C2 + C + t];
    ks[t] = ka;
    __syncthreads();
    const float* wrow = Wqkv + (size_t)t * C2;
    float ua = 0.f;
    for (int j = 0; j < C; j++) ua += wrow[j] * ks[j];
    d_u[b * C + t] = ua;
}

// ---------------------------------------------------------------------------
// K3: scores (verbatim R2 — proven rounding).
// ---------------------------------------------------------------------------
__global__ void k_scores(const float* __restrict__ X,
                         const float* __restrict__ mask) {
    int b = blockIdx.y, t = threadIdx.x;
    __shared__ float us[C];
    us[t] = d_u[b * C + t];
    __syncthreads();
    int warp = t >> 5, lane = t & 31;
    int n = blockIdx.x * 8 + warp;
    const float4* xr = (const float4*)(X + ((size_t)b * N + n) * C);
    const float4* ur = (const float4*)us;
    float acc = 0.f;
    #pragma unroll
    for (int it = 0; it < 2; it++) {
        float4 xv = xr[lane + it * 32];
        float4 uv = ur[lane + it * 32];
        acc += xv.x * uv.x + xv.y * uv.y + xv.z * uv.z + xv.w * uv.w;
    }
    #pragma unroll
    for (int o = 16; o; o >>= 1) acc += __shfl_xor_sync(0xffffffffu, acc, o);
    if (lane == 0) {
        float m = mask[b * N + n];
        d_scores[b * N + n] = (m > 0.f) ? SCALE * acc : -1e9f;
    }
}

// ---------------------------------------------------------------------------
// K4: top-k. Hybrid bitonic with PING-PONG shared buffers: each cross-warp
// stage reads the old buffer and writes the other -> 1 barrier per stage
// (+1 refill per phase), vs 2 per stage before. Sort is exact integer
// comparison: output bit-identical to the R2-proven kernel.
// Key = (~orderedFloat(score) << 32) | idx ; ascending == desc score,
// ascending index tie-break (matches jax.lax.top_k).
// ---------------------------------------------------------------------------
__global__ void __launch_bounds__(1024, 1)
k_topk(const float* __restrict__ mask, float* __restrict__ out) {
    int b = blockIdx.x, t = threadIdx.x;
    __shared__ unsigned long long buf[2][N];   // ping-pong (16KB)
    __shared__ float red[32];
    __shared__ int s_ki;

    float f = d_scores[b * N + t];
    unsigned u = __float_as_uint(f);
    u = (u & 0x80000000u) ? ~u : (u | 0x80000000u);
    unsigned long long v = ((unsigned long long)(~u) << 32) | (unsigned)t;

    // mask sum -> k_i (exact: 0/1 values)
    float ms = mask[b * N + t];
    #pragma unroll
    for (int o = 16; o; o >>= 1) ms += __shfl_xor_sync(0xffffffffu, ms, o);
    if ((t & 31) == 0) red[t >> 5] = ms;
    if (t == 0) {
        // red written by this warp's own lane0 path? ensure after barrier below
    }

    int cur = 0;
    buf[0][t] = v;
    __syncthreads();
    if (t == 0) {
        float s = 0.f;
        #pragma unroll
        for (int w = 0; w < 32; w++) s += red[w];
        s_ki = (int)ceilf(0.25f * s);
    }

    #pragma unroll
    for (unsigned k = 2; k <= 1024; k <<= 1) {
        bool dir_up = ((t & k) == 0);
        bool had_shared = false;
        for (unsigned j = k >> 1; j >= 32; j >>= 1) {
            // buf[cur] holds current values (== v at own slot)
            unsigned long long w = buf[cur][t ^ j];
            bool lower = ((t & j) == 0);
            bool takeMin = (lower == dir_up);
            v = takeMin ? (v < w ? v : w) : (v > w ? v : w);
            buf[cur ^ 1][t] = v;
            cur ^= 1;
            __syncthreads();
            had_shared = true;
        }
        unsigned jstart = (k >> 1) < 16u ? (k >> 1) : 16u;
        for (unsigned j = jstart; j >= 1; j >>= 1) {
            unsigned long long w = __shfl_xor_sync(0xffffffffu, v, j);
            bool lower = ((t & j) == 0);
            bool takeMin = (lower == dir_up);
            v = takeMin ? (v < w ? v : w) : (v > w ? v : w);
        }
        // refill shared with post-warp-stage values for the next phase
        if (k < 1024) {
            buf[cur][t] = v;
            __syncthreads();
        }
        (void)had_shared;
    }

    // publish final sorted order
    buf[cur][t] = v;
    __syncthreads();

    if (t < K) {
        unsigned long long key = buf[cur][t];
        int n = (int)(unsigned)key;
        unsigned uh = ~(unsigned)(key >> 32);
        unsigned orig = (uh & 0x80000000u) ? (uh & 0x7fffffffu) : ~uh;
        float val = __uint_as_float(orig);
        float nm = (t < s_ki) ? 1.f : 0.f;
        d_idxg[b * K + t] = n;
        d_gate[b * K + t] = tanhf(val) * nm;
        d_nm[b * K + t]   = nm;
        out[OUT_MASK_OFF + b * K + t] = nm;
    }
}

// ---------------------------------------------------------------------------
// K5: gather, 4 output rows per block. grid (64, 8), 256 threads.
//   new_X[b,i,:]   = X[b, idx[i], :] * gate[i]
//   new_adj[b,i,j] = adj[b, idx[i], idx[j]] * nm[i]*nm[j]
// 4 adj rows (16KB) staged coalesced -> more loads in flight, fewer barriers.
// ---------------------------------------------------------------------------
__global__ void __launch_bounds__(256, 4)
k_gather(const float* __restrict__ X,
         const float* __restrict__ adj,
         float* __restrict__ out) {
    int b = blockIdx.y, i0 = blockIdx.x * 4, t = threadIdx.x;
    __shared__ int   sidx[K];
    __shared__ float snm[K];
    __shared__ __align__(16) float srow[4][N];
    sidx[t] = d_idxg[b * K + t];
    snm[t]  = d_nm[b * K + t];
    __syncthreads();

    int   ri[4];
    float nmi[4], gte[4];
    #pragma unroll
    for (int r = 0; r < 4; r++) {
        ri[r]  = sidx[i0 + r];
        nmi[r] = snm[i0 + r];
        gte[r] = d_gate[b * K + i0 + r];
    }

    // stage 4 adj rows coalesced (float4); 4 independent LDGs in flight
    #pragma unroll
    for (int r = 0; r < 4; r++) {
        const float4* row4 = (const float4*)(adj + (size_t)b * N * N + (size_t)ri[r] * N);
        ((float4*)srow[r])[t] = row4[t];
    }
    // new_X rows (coalesced), overlapped with adj staging latency
    #pragma unroll
    for (int r = 0; r < 4; r++)
        out[((size_t)b * K + i0 + r) * C + t] = X[((size_t)b * N + ri[r]) * C + t] * gte[r];
    __syncthreads();

    int   cj  = sidx[t];
    float nmj = snm[t];
    #pragma unroll
    for (int r = 0; r < 4; r++)
        out[OUT_ADJ_OFF + ((size_t)b * K + i0 + r) * K + t] = srow[r][cj] * nmi[r] * nmj;
}

// ---------------------------------------------------------------------------
extern "C" void kernel_launch(void* const* d_in, const int* in_sizes, int n_in,
                              void* d_out, int out_size) {
    const float* X    = (const float*)d_in[0];
    const float* adj  = (const float*)d_in[1];
    const float* mask = (const float*)d_in[2];
    const float* Wqkv = (const float*)d_in[3];
    float* out = (float*)d_out;

    k_partial<<<dim3(NCHUNK, B), 256>>>(X);
    k_uvec<<<B, 256>>>(Wqkv);
    k_scores<<<dim3(N / 8, B), 256>>>(X, mask);
    k_topk<<<B, 1024>>>(mask, out);
    k_gather<<<dim3(K / 4, B), 256>>>(X, adj, out);
}

// round 6
// speedup vs baseline: 1.6935x; 1.6935x over previous
#include <cuda_runtime.h>
#include <math.h>

#define B 8
#define N 1024
#define C 256
#define K 256
#define C2 512
#define SCALE 0.17677669529663687f   // (C/H)^-0.5 = 1/sqrt(32)

// Output layout: [new_X (8*256*256) | new_adj (8*256*256) | new_mask (8*256)]
#define OUT_ADJ_OFF  (B*K*C)
#define OUT_MASK_OFF (2*B*K*C)

#define NCHUNK 64      // partial-sum chunks per batch (16 rows each)

// ---- scratch ----
__device__ float d_part[B*NCHUNK*C];
__device__ float d_u[B*C];
__device__ float d_scores[B*N];
__device__ int   d_idxg[B*K];
__device__ float d_gate[B*K];
__device__ float d_nm[B*K];

// ---------------------------------------------------------------------------
// K1: partial column sums of X (verbatim R2 — proven rounding).
// ---------------------------------------------------------------------------
__global__ void k_partial(const float* __restrict__ X) {
    int b = blockIdx.y, ch = blockIdx.x, c = threadIdx.x;
    const float* xp = X + ((size_t)b * N + (size_t)ch * 16) * C + c;
    float s = 0.f;
    #pragma unroll
    for (int r = 0; r < 16; r++) s += xp[(size_t)r * C];
    d_part[(b * NCHUNK + ch) * C + c] = s;
}

// ---------------------------------------------------------------------------
// K2: Xsum finish + two matvecs (verbatim R2 — proven rounding).
// ---------------------------------------------------------------------------
__global__ void k_uvec(const float* __restrict__ Wqkv) {
    int b = blockIdx.x, t = threadIdx.x;
    __shared__ float xs[C];
    __shared__ float ks[C];
    float s = 0.f;
    #pragma unroll
    for (int ch = 0; ch < NCHUNK; ch++) s += d_part[(b * NCHUNK + ch) * C + t];
    xs[t] = s;
    __syncthreads();
    float ka = 0.f;
    for (int c = 0; c < C; c++) ka += xs[c] * Wqkv[(size_t)c * C2 + C + t];
    ks[t] = ka;
    __syncthreads();
    const float* wrow = Wqkv + (size_t)t * C2;
    float ua = 0.f;
    for (int j = 0; j < C; j++) ua += wrow[j] * ks[j];
    d_u[b * C + t] = ua;
}

// ---------------------------------------------------------------------------
// K3: scores (verbatim R2 — proven rounding).
// ---------------------------------------------------------------------------
__global__ void k_scores(const float* __restrict__ X,
                         const float* __restrict__ mask) {
    int b = blockIdx.y, t = threadIdx.x;
    __shared__ float us[C];
    us[t] = d_u[b * C + t];
    __syncthreads();
    int warp = t >> 5, lane = t & 31;
    int n = blockIdx.x * 8 + warp;
    const float4* xr = (const float4*)(X + ((size_t)b * N + n) * C);
    const float4* ur = (const float4*)us;
    float acc = 0.f;
    #pragma unroll
    for (int it = 0; it < 2; it++) {
        float4 xv = xr[lane + it * 32];
        float4 uv = ur[lane + it * 32];
        acc += xv.x * uv.x + xv.y * uv.y + xv.z * uv.z + xv.w * uv.w;
    }
    #pragma unroll
    for (int o = 16; o; o >>= 1) acc += __shfl_xor_sync(0xffffffffu, acc, o);
    if (lane == 0) {
        float m = mask[b * N + n];
        d_scores[b * N + n] = (m > 0.f) ? SCALE * acc : -1e9f;
    }
}

// ---------------------------------------------------------------------------
// K4: top-k. 8-elements-per-thread in-register bitonic, 128 threads.
// Element e = 8t + r, key v[r]. For stage (k, j):
//   partner(e) = e ^ j; lower = ((e&j)==0); up = ((e&k)==0);
//   lower element takes min iff up (standard ascending bitonic).
// j<8   : both elements in-thread (register min/max, no comm).
// 8<=j<=128 : partner thread t^(j/8), same r -> shfl_xor (no barrier).
// j in {256,512} : cross-warp -> padded shared roundtrip (only 3 such stages).
// Keys identical to R2's proven kernel; integer sort => bit-identical result.
// ---------------------------------------------------------------------------
__global__ void __launch_bounds__(128, 1)
k_topk(const float* __restrict__ mask, float* __restrict__ out) {
    int b = blockIdx.x, t = threadIdx.x;
    __shared__ unsigned long long sx[128 * 9];   // stride 9 kills bank conflicts
    __shared__ float red[4];
    __shared__ int s_ki;

    unsigned long long v[8];
    float msum = 0.f;
    {
        const float* sc = d_scores + b * N + t * 8;
        const float* mk = mask + b * N + t * 8;
        #pragma unroll
        for (int r = 0; r < 8; r++) {
            float f = sc[r];
            unsigned u = __float_as_uint(f);
            u = (u & 0x80000000u) ? ~u : (u | 0x80000000u);
            v[r] = ((unsigned long long)(~u) << 32) | (unsigned)(t * 8 + r);
            msum += mk[r];
        }
    }
    // mask sum -> k_i (0/1 values: exact in any order)
    #pragma unroll
    for (int o = 16; o; o >>= 1) msum += __shfl_xor_sync(0xffffffffu, msum, o);
    if ((t & 31) == 0) red[t >> 5] = msum;
    __syncthreads();
    if (t == 0) s_ki = (int)ceilf(0.25f * (red[0] + red[1] + red[2] + red[3]));
    __syncthreads();

    #pragma unroll
    for (unsigned k = 2; k <= 1024; k <<= 1) {
        #pragma unroll
        for (unsigned j = 512; j > 0; j >>= 1) {
            if (j > (k >> 1)) continue;          // stage not in this phase
            if (j >= 256) {
                // shared exchange: partner thread t ^ (j/8), same r
                unsigned jt = j >> 3;
                __syncthreads();
                #pragma unroll
                for (int r = 0; r < 8; r++) sx[t * 9 + r] = v[r];
                __syncthreads();
                bool lower = ((t & jt) == 0);          // == ((e&j)==0)
                bool up    = ((t & (k >> 3)) == 0);    // == ((e&k)==0), k>=16
                bool takeMin = (lower == up);
                #pragma unroll
                for (int r = 0; r < 8; r++) {
                    unsigned long long w = sx[(t ^ jt) * 9 + r];
                    v[r] = takeMin ? (v[r] < w ? v[r] : w)
                                   : (v[r] > w ? v[r] : w);
                }
            } else if (j >= 8) {
                // warp shuffle exchange: lane distance j/8 <= 16
                unsigned jt = j >> 3;
                bool lower = ((t & jt) == 0);
                bool up    = ((t & (k >> 3)) == 0);    // k >= 16 here
                bool takeMin = (lower == up);
                #pragma unroll
                for (int r = 0; r < 8; r++) {
                    unsigned long long w = __shfl_xor_sync(0xffffffffu, v[r], jt);
                    v[r] = takeMin ? (v[r] < w ? v[r] : w)
                                   : (v[r] > w ? v[r] : w);
                }
            } else {
                // in-thread exchange on register pairs (r, r|j)
                #pragma unroll
                for (int r = 0; r < 8; r++) {
                    if ((r & j) == 0) {
                        int rp = r | j;
                        unsigned e = (unsigned)(t * 8 + r);   // lower index
                        bool up = ((e & k) == 0);
                        unsigned long long a = v[r], bb = v[rp];
                        unsigned long long mn = a < bb ? a : bb;
                        unsigned long long mx = a < bb ? bb : a;
                        v[r]  = up ? mn : mx;
                        v[rp] = up ? mx : mn;
                    }
                }
            }
        }
    }

    // elements 0..255 (ascending key == descending score, index tie-break,
    // matching jax.lax.top_k) live in threads 0..31
    if (t < 32) {
        #pragma unroll
        for (int r = 0; r < 8; r++) {
            int pos = t * 8 + r;
            unsigned long long key = v[r];
            int n = (int)(unsigned)key;
            unsigned uh = ~(unsigned)(key >> 32);   // recover score bits
            unsigned orig = (uh & 0x80000000u) ? (uh & 0x7fffffffu) : ~uh;
            float val = __uint_as_float(orig);
            float nm = (pos < s_ki) ? 1.f : 0.f;
            d_idxg[b * K + pos] = n;
            d_gate[b * K + pos] = tanhf(val) * nm;
            d_nm[b * K + pos]   = nm;
            out[OUT_MASK_OFF + b * K + pos] = nm;
        }
    }
}

// ---------------------------------------------------------------------------
// K5: gather (verbatim R4 — measured 7.9us). grid (K, B), 256 threads.
//   new_X[b,i,:]   = X[b, idx[i], :] * gate[i]          (coalesced)
//   new_adj[b,i,j] = adj[b, idx[i], idx[j]] * nm[i]*nm[j]
// adj row staged in shared via coalesced float4 loads, then LDS gather.
// ---------------------------------------------------------------------------
__global__ void k_gather(const float* __restrict__ X,
                         const float* __restrict__ adj,
                         float* __restrict__ out) {
    int b = blockIdx.y, i = blockIdx.x, t = threadIdx.x;
    __shared__ int   sidx[K];
    __shared__ float snm[K];
    __shared__ __align__(16) float srow[N];
    sidx[t] = d_idxg[b * K + t];
    snm[t]  = d_nm[b * K + t];
    __syncthreads();

    int ri = sidx[i];
    float nmi = snm[i];
    float gte = d_gate[b * K + i];

    {
        const float4* row4 = (const float4*)(adj + (size_t)b * N * N + (size_t)ri * N);
        ((float4*)srow)[t] = row4[t];
    }
    out[((size_t)b * K + i) * C + t] = X[((size_t)b * N + ri) * C + t] * gte;
    __syncthreads();

    out[OUT_ADJ_OFF + ((size_t)b * K + i) * K + t] = srow[sidx[t]] * nmi * snm[t];
}

// ---------------------------------------------------------------------------
extern "C" void kernel_launch(void* const* d_in, const int* in_sizes, int n_in,
                              void* d_out, int out_size) {
    const float* X    = (const float*)d_in[0];
    const float* adj  = (const float*)d_in[1];
    const float* mask = (const float*)d_in[2];
    const float* Wqkv = (const float*)d_in[3];
    float* out = (float*)d_out;

    k_partial<<<dim3(NCHUNK, B), 256>>>(X);
    k_uvec<<<B, 256>>>(Wqkv);
    k_scores<<<dim3(N / 8, B), 256>>>(X, mask);
    k_topk<<<B, 128>>>(mask, out);
    k_gather<<<dim3(K, B), 256>>>(X, adj, out);
}